// round 6
// baseline (speedup 1.0000x reference)
#include <cuda_runtime.h>
#include <cuda_bf16.h>

#define L 4
#define B 128
#define T 1024
#define NI 512
#define H 512
#define G 2048
#define BH (B*H)

#define NBLK 128
#define NTHR 512

// ---- smem layout (bytes) ----
// W: 64 rows x 512 k, hi/lo bf16 planes, row stride 1040B
#define WS_HI 0
#define WS_LO 66560
// x-phase stage: 2 buffers x (hi+lo planes), plane = 128 rows x 144B
#define PS 133120
#define PLANE 18432
#define BUFSTRIDE 36864
// recurrent stage: 32 rows x 512 k hi/lo planes, row stride 1040B
#define RS 133120
#define RPLANE 33280
// gates tile 64 x 32 f32, stride 33
#define GS 206848
#define SMEM_BYTES 215296

// ---- device scratch ----
__device__ unsigned g_x_pack[(size_t)B * T * NI];
__device__ unsigned g_seq_pack[(size_t)T * BH];
__device__ unsigned g_h0_pack[(size_t)L * BH];
__device__ float g_gx[(size_t)B * T * G];           // [b][t][gate]
__device__ unsigned long long g_flags[NBLK];

__device__ __forceinline__ unsigned long long ldvol(const unsigned long long* p) {
    unsigned long long v;
    asm volatile("ld.volatile.global.u64 %0, [%1];" : "=l"(v) : "l"(p));
    return v;
}

// global barrier (prologue only)
__device__ __forceinline__ void gbar_all(unsigned long long ep) {
    __syncthreads();
    __threadfence();
    if (threadIdx.x == 0) atomicExch(&g_flags[blockIdx.x], ep);
    if (threadIdx.x < NBLK) {
        while (ldvol(&g_flags[threadIdx.x]) < ep) { }
    }
    __threadfence();
    __syncthreads();
}

// group barrier: 32 blocks sharing a batch group
__device__ __forceinline__ void gbar_grp(unsigned long long ep, int grp) {
    __syncthreads();
    __threadfence();
    if (threadIdx.x == 0) atomicExch(&g_flags[blockIdx.x], ep);
    if (threadIdx.x < 32) {
        while (ldvol(&g_flags[grp * 32 + threadIdx.x]) < ep) { }
    }
    __threadfence();
    __syncthreads();
}

__device__ __forceinline__ unsigned packf(float v) {
    __nv_bfloat16 h = __float2bfloat16(v);
    float hf = __bfloat162float(h);
    __nv_bfloat16 lo = __float2bfloat16(v - hf);
    unsigned short uh = *(unsigned short*)&h;
    unsigned short ul = *(unsigned short*)&lo;
    return ((unsigned)ul << 16) | (unsigned)uh;
}

__device__ __forceinline__ void ldsm4(unsigned r[4], unsigned addr) {
    asm volatile("ldmatrix.sync.aligned.m8n8.x4.shared.b16 {%0,%1,%2,%3}, [%4];"
                 : "=r"(r[0]), "=r"(r[1]), "=r"(r[2]), "=r"(r[3]) : "r"(addr));
}

__device__ __forceinline__ void mma16816(float c[4], const unsigned a[4],
                                         unsigned b0, unsigned b1) {
    asm volatile(
        "mma.sync.aligned.m16n8k16.row.col.f32.bf16.bf16.f32 "
        "{%0,%1,%2,%3}, {%4,%5,%6,%7}, {%8,%9}, {%0,%1,%2,%3};"
        : "+f"(c[0]), "+f"(c[1]), "+f"(c[2]), "+f"(c[3])
        : "r"(a[0]), "r"(a[1]), "r"(a[2]), "r"(a[3]), "r"(b0), "r"(b1));
}

__device__ __forceinline__ float sigf(float x) { return 1.0f / (1.0f + __expf(-x)); }
__device__ __forceinline__ float tanhg(float x) { return 2.0f / (1.0f + __expf(-2.0f * x)) - 1.0f; }

__device__ __forceinline__ void stage_store(char* bufHi, unsigned off, uint4 p, int plane) {
    unsigned h0_ = __byte_perm(p.x, p.y, 0x5410);
    unsigned h1_ = __byte_perm(p.z, p.w, 0x5410);
    unsigned l0_ = __byte_perm(p.x, p.y, 0x7632);
    unsigned l1_ = __byte_perm(p.z, p.w, 0x7632);
    *(uint2*)(bufHi + off) = make_uint2(h0_, h1_);
    *(uint2*)(bufHi + plane + off) = make_uint2(l0_, l1_);
}

__global__ void __launch_bounds__(NTHR, 1)
lstm_kernel(const float* __restrict__ x,
            const float* __restrict__ h0,
            const float* __restrict__ c0,
            const float* __restrict__ w_ih,
            const float* __restrict__ w_hh,
            const float* __restrict__ b_ih,
            const float* __restrict__ b_hh,
            float* __restrict__ out) {
    extern __shared__ char sm[];
    const unsigned sbase = (unsigned)__cvta_generic_to_shared(sm);
    float* const gates_s = (float*)(sm + GS);

    const int tid = threadIdx.x, bid = blockIdx.x;
    const int lane = tid & 31, warp = tid >> 5;

    unsigned long long ep = ldvol(&g_flags[bid]);

    // ---------------- prologue: pack x, h0 ----------------
    {
        const size_t gt0 = (size_t)bid * NTHR + tid, gs = (size_t)NBLK * NTHR;
        const float4* xs = (const float4*)x;
        const size_t nx = (size_t)B * T * NI / 4;
        for (size_t i = gt0; i < nx; i += gs) {
            float4 v = __ldg(xs + i);
            ((uint4*)g_x_pack)[i] = make_uint4(packf(v.x), packf(v.y), packf(v.z), packf(v.w));
        }
        const float4* hs = (const float4*)h0;
        const size_t nh = (size_t)L * BH / 4;
        for (size_t i = gt0; i < nh; i += gs) {
            float4 v = __ldg(hs + i);
            ((uint4*)g_h0_pack)[i] = make_uint4(packf(v.x), packf(v.y), packf(v.z), packf(v.w));
        }
    }
    gbar_all(++ep);

    const int gt = bid & 31;    // gate/h tile
    const int grp = bid >> 5;   // batch group (32 batches)

    const int wg = warp >> 2, wsub = warp & 3;
    const unsigned wA = sbase + WS_HI + (unsigned)((wg * 16 + (lane & 15)) * 1040 + (lane >> 4) * 16);
    const unsigned wAlo = wA + (WS_LO - WS_HI);
    const unsigned pBx_rel = (unsigned)((wsub * 32 + (lane & 7) + ((lane >> 4) << 3)) * 144
                                        + ((lane >> 3) & 1) * 16);
    // recurrent B frag: batch rows, stride 1040
    const unsigned pBr = sbase + RS + (unsigned)((wsub * 8 + (lane & 7)) * 1040 + (lane >> 3) * 16);

    const int lh = tid & 15, lb = tid >> 4;
    const int eb = grp * 32 + lb;
    const int egh = gt * 16 + lh;

    for (int l = 0; l < L; ++l) {
        // ================= x-phase: gx = W_ih * input_seq =================
        for (int it = tid; it < 64 * 128; it += NTHR) {
            int r = it >> 7, c4 = it & 127;
            float4 v = __ldg((const float4*)(w_ih + ((size_t)l * G + gt * 64 + r) * 512) + c4);
            unsigned p0 = packf(v.x), p1 = packf(v.y), p2 = packf(v.z), p3 = packf(v.w);
            *(uint2*)(sm + WS_HI + r * 1040 + c4 * 8) =
                make_uint2(__byte_perm(p0, p1, 0x5410), __byte_perm(p2, p3, 0x5410));
            *(uint2*)(sm + WS_LO + r * 1040 + c4 * 8) =
                make_uint2(__byte_perm(p0, p1, 0x7632), __byte_perm(p2, p3, 0x7632));
        }
        __syncthreads();

        {
            const int srow = tid >> 2, ssg = tid & 3;
            for (int m = 0; m < 256; ++m) {
                const int bb = grp * 32 + (m >> 3);
                const int t0 = (m & 7) * 128;

                const unsigned* rowp;
                if (l == 0) rowp = g_x_pack + (((size_t)bb << 10) + (size_t)(t0 + srow)) * 512;
                else        rowp = g_seq_pack + ((size_t)((t0 + srow) * 128 + bb)) * 512;

                float acc[4][4];
                #pragma unroll
                for (int f = 0; f < 4; ++f)
                    #pragma unroll
                    for (int q = 0; q < 4; ++q) acc[f][q] = 0.f;

                uint4 rg[4];
                // chunk 0 -> buf0
                #pragma unroll
                for (int q = 0; q < 4; ++q) rg[q] = __ldcg((const uint4*)rowp + ssg + 4 * q);
                #pragma unroll
                for (int q = 0; q < 4; ++q)
                    stage_store(sm + PS, srow * 144 + (ssg + 4 * q) * 8, rg[q], PLANE);
                // prefetch chunk 1
                #pragma unroll
                for (int q = 0; q < 4; ++q) rg[q] = __ldcg((const uint4*)rowp + 16 + ssg + 4 * q);
                __syncthreads();

                #pragma unroll 1
                for (int c = 0; c < 8; ++c) {
                    // store next chunk into the other buffer (overlaps with MMA below)
                    if (c < 7) {
                        char* bufHi = sm + PS + ((c + 1) & 1) * BUFSTRIDE;
                        #pragma unroll
                        for (int q = 0; q < 4; ++q)
                            stage_store(bufHi, srow * 144 + (ssg + 4 * q) * 8, rg[q], PLANE);
                    }
                    if (c < 6) {
                        #pragma unroll
                        for (int q = 0; q < 4; ++q)
                            rg[q] = __ldcg((const uint4*)rowp + (c + 2) * 16 + ssg + 4 * q);
                    }
                    const unsigned bufo = sbase + PS + (c & 1) * BUFSTRIDE;
                    #pragma unroll
                    for (int q = 0; q < 4; ++q) {
                        unsigned ah[4], al[4];
                        ldsm4(ah, wA + c * 128 + q * 32);
                        ldsm4(al, wAlo + c * 128 + q * 32);
                        #pragma unroll
                        for (int u = 0; u < 2; ++u) {
                            unsigned bh[4], bl[4];
                            unsigned ba = bufo + pBx_rel + u * 2304 + q * 32;
                            ldsm4(bh, ba);
                            ldsm4(bl, ba + PLANE);
                            mma16816(acc[2 * u],     ah, bh[0], bh[1]);
                            mma16816(acc[2 * u],     al, bh[0], bh[1]);
                            mma16816(acc[2 * u],     ah, bl[0], bl[1]);
                            mma16816(acc[2 * u + 1], ah, bh[2], bh[3]);
                            mma16816(acc[2 * u + 1], al, bh[2], bh[3]);
                            mma16816(acc[2 * u + 1], ah, bl[2], bl[3]);
                        }
                    }
                    __syncthreads();
                }

                const size_t cb = ((size_t)bb << 10) + (size_t)t0;
                const int gr0 = gt * 64 + wg * 16 + (lane >> 2);
                #pragma unroll
                for (int f = 0; f < 4; ++f) {
                    int u = f >> 1, v2 = f & 1;
                    int tt = wsub * 32 + u * 16 + v2 * 8 + (lane & 3) * 2;
                    float* p = g_gx + (cb + tt) * G + gr0;
                    __stcg(p, acc[f][0]);
                    __stcg(p + G, acc[f][1]);
                    __stcg(p + 8, acc[f][2]);
                    __stcg(p + G + 8, acc[f][3]);
                }
            }
        }
        gbar_grp(++ep, grp);

        // ================= recurrent phase =================
        for (int it = tid; it < 64 * 128; it += NTHR) {
            int r = it >> 7, c4 = it & 127;
            int grow = (r >> 4) * 512 + gt * 16 + (r & 15);
            float4 v = __ldg((const float4*)(w_hh + ((size_t)l * G + grow) * 512) + c4);
            unsigned p0 = packf(v.x), p1 = packf(v.y), p2 = packf(v.z), p3 = packf(v.w);
            *(uint2*)(sm + WS_HI + r * 1040 + c4 * 8) =
                make_uint2(__byte_perm(p0, p1, 0x5410), __byte_perm(p2, p3, 0x5410));
            *(uint2*)(sm + WS_LO + r * 1040 + c4 * 8) =
                make_uint2(__byte_perm(p0, p1, 0x7632), __byte_perm(p2, p3, 0x7632));
        }
        __syncthreads();

        float bias[4];
        #pragma unroll
        for (int g = 0; g < 4; ++g)
            bias[g] = __ldg(b_ih + (size_t)l * G + g * 512 + egh)
                    + __ldg(b_hh + (size_t)l * G + g * 512 + egh);
        float creg = __ldg(c0 + (size_t)l * BH + (size_t)eb * 512 + egh);
        const float* gx_base = g_gx + ((size_t)eb << 10) * G + egh;

        const int hrow = tid >> 4, hsg = tid & 15;  // 32 rows x 16 uint4 segs

        for (int t = 0; t < T; ++t) {
            // prefetch gx for EW (hides L2/DRAM latency under MMA phase)
            const float* gxt = gx_base + (size_t)t * G;
            float gx0 = __ldcg(gxt);
            float gx1 = __ldcg(gxt + 512);
            float gx2 = __ldcg(gxt + 1024);
            float gx3 = __ldcg(gxt + 1536);

            const unsigned* rowp;
            if (t == 0) rowp = g_h0_pack + ((size_t)(l * 128 + grp * 32 + hrow)) * 512;
            else        rowp = g_seq_pack + ((size_t)((t - 1) * 128 + grp * 32 + hrow)) * 512;

            uint4 hrg[8];
            #pragma unroll
            for (int c = 0; c < 8; ++c)
                hrg[c] = __ldcg((const uint4*)rowp + c * 16 + hsg);

            // stage whole 32x512 h tile (hi/lo), single sync
            #pragma unroll
            for (int c = 0; c < 8; ++c)
                stage_store(sm + RS, hrow * 1040 + (c * 16 + hsg) * 8, hrg[c], RPLANE);
            __syncthreads();

            float a0[4] = {0.f, 0.f, 0.f, 0.f}, a1[4] = {0.f, 0.f, 0.f, 0.f};
            #pragma unroll
            for (int c = 0; c < 8; ++c) {
                #pragma unroll
                for (int g2 = 0; g2 < 2; ++g2) {
                    unsigned bh[4], bl[4], ah0[4], ah1[4], al0[4], al1[4];
                    unsigned ba = pBr + c * 128 + g2 * 64;
                    ldsm4(bh, ba);
                    ldsm4(bl, ba + RPLANE);
                    ldsm4(ah0, wA + c * 128 + g2 * 64);
                    ldsm4(ah1, wA + c * 128 + g2 * 64 + 32);
                    ldsm4(al0, wAlo + c * 128 + g2 * 64);
                    ldsm4(al1, wAlo + c * 128 + g2 * 64 + 32);
                    mma16816(a0, ah0, bh[0], bh[1]);
                    mma16816(a1, al0, bh[0], bh[1]);
                    mma16816(a1, ah0, bl[0], bl[1]);
                    mma16816(a0, ah1, bh[2], bh[3]);
                    mma16816(a1, al1, bh[2], bh[3]);
                    mma16816(a1, ah1, bl[2], bl[3]);
                }
            }

            {
                int gr = wg * 16 + (lane >> 2);
                int gc = wsub * 8 + (lane & 3) * 2;
                gates_s[gr * 33 + gc]           = a0[0] + a1[0];
                gates_s[gr * 33 + gc + 1]       = a0[1] + a1[1];
                gates_s[(gr + 8) * 33 + gc]     = a0[2] + a1[2];
                gates_s[(gr + 8) * 33 + gc + 1] = a0[3] + a1[3];
            }
            __syncthreads();

            {
                float v0 = bias[0] + gates_s[(0 * 16 + lh) * 33 + lb] + gx0;
                float v1 = bias[1] + gates_s[(1 * 16 + lh) * 33 + lb] + gx1;
                float v2 = bias[2] + gates_s[(2 * 16 + lh) * 33 + lb] + gx2;
                float v3 = bias[3] + gates_s[(3 * 16 + lh) * 33 + lb] + gx3;
                float ig = sigf(v0), fg = sigf(v1), gg = tanhg(v2), og = sigf(v3);
                creg = fmaf(fg, creg, ig * gg);
                float hv = og * tanhg(creg);
                g_seq_pack[((size_t)t * 128 + eb) * 512 + egh] = packf(hv);
                if (t == T - 1)
                    out[(size_t)l * BH + (size_t)eb * 512 + egh] = creg;
            }
            gbar_grp(++ep, grp);
        }
    }
}

extern "C" void kernel_launch(void* const* d_in, const int* in_sizes, int n_in,
                              void* d_out, int out_size) {
    const float* x    = (const float*)d_in[0];
    const float* h0   = (const float*)d_in[1];
    const float* c0   = (const float*)d_in[2];
    const float* w_ih = (const float*)d_in[3];
    const float* w_hh = (const float*)d_in[4];
    const float* b_ih = (const float*)d_in[5];
    const float* b_hh = (const float*)d_in[6];
    float* out = (float*)d_out;

    cudaFuncSetAttribute(lstm_kernel,
                         cudaFuncAttributeMaxDynamicSharedMemorySize, SMEM_BYTES);
    lstm_kernel<<<NBLK, NTHR, SMEM_BYTES>>>(x, h0, c0, w_ih, w_hh, b_ih, b_hh, out);
}